// round 9
// baseline (speedup 1.0000x reference)
#include <cuda_runtime.h>
#include <cuda_bf16.h>
#include <cstdint>

#define N_NODES 100000
#define N_EDGES 1600000
#define HID 128

// ---------------- scratch (device globals; no allocation) ----------------
__device__ float g_cnt [N_NODES];
__device__ float g_agg1[N_NODES * 6];
__device__ float g_h1  [N_NODES * HID];
__device__ float g_agg2[N_NODES * HID];
__device__ float g_p   [N_NODES * HID];   // h2 @ W_e1[0:128]
__device__ float g_q   [N_NODES * HID];   // h2 @ W_e1[128:256]

// ---------------- warp MMA helpers (baseline PTX) ----------------
__device__ __forceinline__ uint32_t smem_u32(const void* p) {
    uint32_t a;
    asm("{ .reg .u64 t; cvta.to.shared.u64 t, %1; cvt.u32.u64 %0, t; }" : "=r"(a) : "l"(p));
    return a;
}
__device__ __forceinline__ void mma16816(float* d, const uint32_t* a, const uint32_t* b) {
    asm volatile(
        "mma.sync.aligned.m16n8k16.row.col.f32.bf16.bf16.f32 "
        "{%0,%1,%2,%3}, {%4,%5,%6,%7}, {%8,%9}, {%0,%1,%2,%3};"
        : "+f"(d[0]), "+f"(d[1]), "+f"(d[2]), "+f"(d[3])
        : "r"(a[0]), "r"(a[1]), "r"(a[2]), "r"(a[3]), "r"(b[0]), "r"(b[1]));
}
__device__ __forceinline__ void ldsm4(uint32_t* r, uint32_t addr) {
    asm volatile("ldmatrix.sync.aligned.m8n8.x4.shared.b16 {%0,%1,%2,%3}, [%4];"
                 : "=r"(r[0]), "=r"(r[1]), "=r"(r[2]), "=r"(r[3]) : "r"(addr));
}
__device__ __forceinline__ uint32_t pack_bf16(float x, float y) {
    __nv_bfloat16 bx = __float2bfloat16(x), by = __float2bfloat16(y);
    return ((uint32_t)__bfloat16_as_ushort(by) << 16) | __bfloat16_as_ushort(bx);
}

// ---------------- zero scratch accumulators ----------------
__global__ void k_zero() {
    int i = blockIdx.x * 256 + threadIdx.x;
    float4 z = make_float4(0.f, 0.f, 0.f, 0.f);
    if (i < N_NODES * HID / 4) reinterpret_cast<float4*>(g_agg2)[i] = z;
    if (i < N_NODES * 6 / 4)   reinterpret_cast<float4*>(g_agg1)[i] = z;
    if (i < N_NODES / 4)       reinterpret_cast<float4*>(g_cnt)[i]  = z;
}

// ---------------- SAGE layer 1 scatter ----------------
__global__ void k_agg1(const float* __restrict__ x, const int* __restrict__ ei) {
    int e = blockIdx.x * 256 + threadIdx.x;
    int s = ei[e];
    int d = ei[N_EDGES + e];
    atomicAdd(&g_cnt[d], 1.0f);
    const float2* xr = reinterpret_cast<const float2*>(x + s * 6);
    float* dst = &g_agg1[d * 6];
#pragma unroll
    for (int k = 0; k < 3; k++) {
        float2 v = xr[k];
        asm volatile("red.global.add.v2.f32 [%0], {%1, %2};"
                     :: "l"(dst + k * 2), "f"(v.x), "f"(v.y) : "memory");
    }
}

// ---------------- h1 = relu(x@W1r + mean1@W1n + b1) ----------------
__global__ void k_h1(const float* __restrict__ x,
                     const float* __restrict__ w1r, const float* __restrict__ w1n,
                     const float* __restrict__ b1) {
    int t = threadIdx.x;
    int node = blockIdx.x * 2 + (t >> 7);
    int j = t & 127;
    float inv = 1.0f / fmaxf(g_cnt[node], 1.0f);
    float acc = b1[j];
#pragma unroll
    for (int k = 0; k < 6; k++) {
        acc += x[node * 6 + k] * w1r[k * 128 + j]
             + g_agg1[node * 6 + k] * inv * w1n[k * 128 + j];
    }
    g_h1[node * 128 + j] = fmaxf(acc, 0.f);
}

// ---------------- scatter h1[src] into agg2 (vector red) ----------------
__global__ void k_agg2(const int* __restrict__ ei) {
    int w = blockIdx.x * 8 + (threadIdx.x >> 5);
    int lane = threadIdx.x & 31;
    int s = ei[w];
    int d = ei[N_EDGES + w];
    float4 v = *reinterpret_cast<const float4*>(&g_h1[s * 128 + lane * 4]);
    float* dst = &g_agg2[d * 128 + lane * 4];
    asm volatile("red.global.add.v4.f32 [%0], {%1, %2, %3, %4};"
                 :: "l"(dst), "f"(v.x), "f"(v.y), "f"(v.z), "f"(v.w) : "memory");
}

// ================= fused node kernel: h2 + p/q, all HMMA ======================
// Phase A: acc = [h1 | mean] @ [W2r ; W2n]   (K = 2 chunks of 128, N = 128)
// Phase B: h2 = relu(acc + b2) -> split bf16 into A smem (never hits global)
// Phase C: p = h2@Wa, q = h2@Wb  (2 N-chunks of 128), direct reg->global stores
// bf16 2-term error split (3 mma terms) throughout.
#define NROW 136                       // padded row, bf16 elems (272 B)
#define SM_N_AHI 0                     // 128*272 = 34816
#define SM_N_ALO 34816
#define SM_N_BHI 69632
#define SM_N_BLO 104448
#define SM_N_B2  139264                // float[128]
#define SM_NODE_TOTAL 139776

// one K=128 HMMA pass: acc[2][8][4] += Ahi*Bhi + Ahi*Blo + Alo*Bhi
__device__ __forceinline__ void mma_k128(float (*acc)[8][4], uint32_t smem_base,
                                         int wm, int wn, int lrow, int lcol,
                                         int bn_base, int b_khalf) {
#pragma unroll
    for (int kk = 0; kk < 8; kk++) {
        uint32_t ahi[2][4], alo[2][4];
        uint32_t aoff = (uint32_t)(wm * 32 + lrow) * (NROW * 2)
                      + (uint32_t)(kk * 16 + lcol) * 2;
        ldsm4(ahi[0], smem_base + SM_N_AHI + aoff);
        ldsm4(ahi[1], smem_base + SM_N_AHI + aoff + 16 * (NROW * 2));
        ldsm4(alo[0], smem_base + SM_N_ALO + aoff);
        ldsm4(alo[1], smem_base + SM_N_ALO + aoff + 16 * (NROW * 2));
        uint32_t bh[4][4], bl[4][4];
#pragma unroll
        for (int g = 0; g < 4; g++) {
            uint32_t boff = (uint32_t)(wn * 64 + g * 16 + bn_base) * (NROW * 2)
                          + (uint32_t)(kk * 16 + b_khalf * 8) * 2;
            ldsm4(bh[g], smem_base + SM_N_BHI + boff);
            ldsm4(bl[g], smem_base + SM_N_BLO + boff);
        }
#pragma unroll
        for (int mi = 0; mi < 2; mi++) {
#pragma unroll
            for (int nn = 0; nn < 8; nn++) {
                const uint32_t* bhf = &bh[nn >> 1][(nn & 1) * 2];
                const uint32_t* blf = &bl[nn >> 1][(nn & 1) * 2];
                mma16816(acc[mi][nn], ahi[mi], bhf);
                mma16816(acc[mi][nn], ahi[mi], blf);
                mma16816(acc[mi][nn], alo[mi], bhf);
            }
        }
    }
}

// stage BT[n][k] = W[k*128+n] split hi/lo into smem (coalesced global reads)
__device__ __forceinline__ void stage_bt(char* smem, const float* __restrict__ W, int t) {
#pragma unroll
    for (int i = 0; i < 16; i++) {
        int idx = i * 256 + t;
        int k = idx >> 5;
        int n4 = (idx & 31) * 4;
        float4 w = *reinterpret_cast<const float4*>(&W[k * 128 + n4]);
        float wv[4] = {w.x, w.y, w.z, w.w};
#pragma unroll
        for (int j = 0; j < 4; j++) {
            float h = __bfloat162float(__float2bfloat16(wv[j]));
            uint32_t off = (uint32_t)(n4 + j) * (NROW * 2) + (uint32_t)k * 2;
            *(__nv_bfloat16*)(smem + SM_N_BHI + off) = __float2bfloat16(h);
            *(__nv_bfloat16*)(smem + SM_N_BLO + off) = __float2bfloat16(wv[j] - h);
        }
    }
}

__global__ __launch_bounds__(256, 1)
void k_node(const float* __restrict__ w2r, const float* __restrict__ w2n,
            const float* __restrict__ b2, const float* __restrict__ we1) {
    extern __shared__ __align__(16) char smem[];
    uint32_t smem_base = smem_u32(smem);
    int t = threadIdx.x;
    int wid = t >> 5, lane = t & 31;
    int wm = wid >> 1;                 // M tile: rows wm*32..+31
    int wn = wid & 1;                  // N half: cols wn*64..+63
    int row0 = blockIdx.x * 128;

    float* b2s = (float*)(smem + SM_N_B2);
    if (t < 128) b2s[t] = b2[t];

    int lrow = (lane & 7) + ((lane & 8) ? 8 : 0);
    int lcol = (lane & 16) ? 8 : 0;
    int bn_base = ((lane >> 4) << 3) + (lane & 7);
    int b_khalf = (lane >> 3) & 1;

    // ---------------- Phase A: h2 accumulation ----------------
    float acc[2][8][4];
#pragma unroll
    for (int mi = 0; mi < 2; mi++)
#pragma unroll
        for (int nn = 0; nn < 8; nn++)
#pragma unroll
            for (int r = 0; r < 4; r++) acc[mi][nn][r] = 0.f;

#pragma unroll 1
    for (int kc = 0; kc < 2; kc++) {
        // stage A chunk (warp-per-row, coalesced)
#pragma unroll
        for (int i = 0; i < 16; i++) {
            int row = i * 8 + wid;
            int grow = row0 + row;
            float v[4] = {0.f, 0.f, 0.f, 0.f};
            if (grow < N_NODES) {
                const float* src = kc ? &g_agg2[grow * 128] : &g_h1[grow * 128];
                float4 a = *reinterpret_cast<const float4*>(&src[lane * 4]);
                float sc = kc ? (1.0f / fmaxf(g_cnt[grow], 1.0f)) : 1.0f;
                v[0] = a.x * sc; v[1] = a.y * sc; v[2] = a.z * sc; v[3] = a.w * sc;
            }
            float hv[4];
#pragma unroll
            for (int j = 0; j < 4; j++) hv[j] = __bfloat162float(__float2bfloat16(v[j]));
            uint2 hp, lp;
            hp.x = pack_bf16(hv[0], hv[1]); hp.y = pack_bf16(hv[2], hv[3]);
            lp.x = pack_bf16(v[0] - hv[0], v[1] - hv[1]);
            lp.y = pack_bf16(v[2] - hv[2], v[3] - hv[3]);
            uint32_t off = (uint32_t)row * (NROW * 2) + (uint32_t)(lane * 4) * 2;
            *(uint2*)(smem + SM_N_AHI + off) = hp;
            *(uint2*)(smem + SM_N_ALO + off) = lp;
        }
        // stage B chunk
        stage_bt(smem, kc ? w2n : w2r, t);
        __syncthreads();
        mma_k128(acc, smem_base, wm, wn, lrow, lcol, bn_base, b_khalf);
        __syncthreads();
    }

    // ---------------- Phase B: h2 = relu(acc+b2) -> A smem split ----------------
#pragma unroll
    for (int mi = 0; mi < 2; mi++) {
#pragma unroll
        for (int nn = 0; nn < 8; nn++) {
#pragma unroll
            for (int rp = 0; rp < 2; rp++) {
                int row = wm * 32 + mi * 16 + (lane >> 2) + rp * 8;
                int col = wn * 64 + nn * 8 + (lane & 3) * 2;
                float v0 = fmaxf(acc[mi][nn][rp * 2 + 0] + b2s[col], 0.f);
                float v1 = fmaxf(acc[mi][nn][rp * 2 + 1] + b2s[col + 1], 0.f);
                float h0 = __bfloat162float(__float2bfloat16(v0));
                float h1 = __bfloat162float(__float2bfloat16(v1));
                uint32_t off = (uint32_t)row * (NROW * 2) + (uint32_t)col * 2;
                *(uint32_t*)(smem + SM_N_AHI + off) = pack_bf16(h0, h1);
                *(uint32_t*)(smem + SM_N_ALO + off) = pack_bf16(v0 - h0, v1 - h1);
            }
        }
    }
    __syncthreads();

    // ---------------- Phase C: p = h2@Wa, q = h2@Wb ----------------
#pragma unroll 1
    for (int nc = 0; nc < 2; nc++) {
        stage_bt(smem, we1 + nc * 128 * 128, t);
        __syncthreads();

        float acc2[2][8][4];
#pragma unroll
        for (int mi = 0; mi < 2; mi++)
#pragma unroll
            for (int nn = 0; nn < 8; nn++)
#pragma unroll
                for (int r = 0; r < 4; r++) acc2[mi][nn][r] = 0.f;

        mma_k128(acc2, smem_base, wm, wn, lrow, lcol, bn_base, b_khalf);

        float* dst = nc ? g_q : g_p;
#pragma unroll
        for (int mi = 0; mi < 2; mi++) {
#pragma unroll
            for (int nn = 0; nn < 8; nn++) {
#pragma unroll
                for (int rp = 0; rp < 2; rp++) {
                    int row = wm * 32 + mi * 16 + (lane >> 2) + rp * 8;
                    int grow = row0 + row;
                    if (grow < N_NODES) {
                        int col = wn * 64 + nn * 8 + (lane & 3) * 2;
                        float2 v = make_float2(acc2[mi][nn][rp * 2 + 0],
                                               acc2[mi][nn][rp * 2 + 1]);
                        *reinterpret_cast<float2*>(&dst[grow * 128 + col]) = v;
                    }
                }
            }
        }
        __syncthreads();
    }
}

// ================= edge MLP via warp HMMA (bf16 2-term split, smem B) =========
#define AROW 136
#define SM_A_HI   0
#define SM_A_LO   34816
#define SM_B_HI   69632
#define SM_B_LO   87040
#define SM_PA     104448
#define SM_PB     104960
#define SM_B2S    105472
#define SM_W3S    105728
#define SM_SRC    105984
#define SM_DST    107008
#define SM_EAS    108032
#define SM_EDGE_TOTAL 112128

#define N_TILES (N_EDGES / 128)
#define EDGE_GRID 296

__global__ __launch_bounds__(256, 2)
void k_edge_mma(const int* __restrict__ ei, const float* __restrict__ ea,
                const float* __restrict__ we1, const float* __restrict__ be1,
                const float* __restrict__ we2, const float* __restrict__ be2,
                const float* __restrict__ we3, const float* __restrict__ be3,
                float* __restrict__ out) {
    extern __shared__ __align__(16) char smem[];
    uint32_t smem_base = smem_u32(smem);
    int t = threadIdx.x;
    int wid = t >> 5, lane = t & 31;
    int wm = wid >> 1;
    int wn = wid & 1;

    float* pa  = (float*)(smem + SM_PA);
    float* pb  = (float*)(smem + SM_PB);
    float* b2s = (float*)(smem + SM_B2S);
    float* w3s = (float*)(smem + SM_W3S);
    int*   srcs = (int*)(smem + SM_SRC);
    int*   dsts = (int*)(smem + SM_DST);
    float* eas  = (float*)(smem + SM_EAS);

    if (t < 64) { b2s[t] = be2[t]; w3s[t] = we3[t]; }

    int kq = lane * 4;
    float4 b1v = *reinterpret_cast<const float4*>(&be1[kq]);
    float4 wc0 = *reinterpret_cast<const float4*>(&we1[256 * 128 + kq]);
    float4 wc1 = *reinterpret_cast<const float4*>(&we1[257 * 128 + kq]);
    float4 wc2 = *reinterpret_cast<const float4*>(&we1[258 * 128 + kq]);
    float4 wc3 = *reinterpret_cast<const float4*>(&we1[259 * 128 + kq]);

    for (int idx = t; idx < 64 * 128; idx += 256) {
        int n = idx >> 7, k = idx & 127;
        float w = we2[k * 64 + n];
        float h = __bfloat162float(__float2bfloat16(w));
        uint32_t off = (uint32_t)n * (AROW * 2) + (uint32_t)k * 2;
        *(__nv_bfloat16*)(smem + SM_B_HI + off) = __float2bfloat16(h);
        *(__nv_bfloat16*)(smem + SM_B_LO + off) = __float2bfloat16(w - h);
    }
    float be3v = be3[0];

    int lrow = (lane & 7) + ((lane & 8) ? 8 : 0);
    int lcol = (lane & 16) ? 8 : 0;
    int b_nrow = wn * 32 + ((lane >> 4) << 3) + (lane & 7);
    int b_khalf = (lane >> 3) & 1;
    uint32_t b_base = (uint32_t)b_nrow * (AROW * 2) + (uint32_t)b_khalf * 16;

    int tile = blockIdx.x;
    {
        int e0 = tile * 128;
        if (t < 128) srcs[t] = ei[e0 + t];
        else         dsts[t - 128] = ei[N_EDGES + e0 + (t - 128)];
        for (int i = t; i < 512; i += 256) eas[i] = ea[e0 * 4 + i];
    }
    __syncthreads();

    int buf = 0;
    for (; tile < N_TILES; tile += EDGE_GRID) {
        int e0 = tile * 128;
        int* sb = srcs + buf * 128;
        int* db = dsts + buf * 128;
        float* eb = eas + buf * 512;

#pragma unroll 4
        for (int i = 0; i < 16; i++) {
            int edge = i * 8 + wid;
            int s = sb[edge], d = db[edge];
            float4 pv = *reinterpret_cast<const float4*>(&g_p[s * 128 + kq]);
            float4 qv = *reinterpret_cast<const float4*>(&g_q[d * 128 + kq]);
            float4 e4 = *reinterpret_cast<const float4*>(&eb[edge * 4]);
            float v[4], hv[4];
            v[0] = pv.x + qv.x + b1v.x + e4.x * wc0.x + e4.y * wc1.x + e4.z * wc2.x + e4.w * wc3.x;
            v[1] = pv.y + qv.y + b1v.y + e4.x * wc0.y + e4.y * wc1.y + e4.z * wc2.y + e4.w * wc3.y;
            v[2] = pv.z + qv.z + b1v.z + e4.x * wc0.z + e4.y * wc1.z + e4.z * wc2.z + e4.w * wc3.z;
            v[3] = pv.w + qv.w + b1v.w + e4.x * wc0.w + e4.y * wc1.w + e4.z * wc2.w + e4.w * wc3.w;
#pragma unroll
            for (int j = 0; j < 4; j++) {
                v[j] = fmaxf(v[j], 0.f);
                hv[j] = __bfloat162float(__float2bfloat16(v[j]));
            }
            uint2 hp, lp;
            hp.x = pack_bf16(hv[0], hv[1]); hp.y = pack_bf16(hv[2], hv[3]);
            lp.x = pack_bf16(v[0] - hv[0], v[1] - hv[1]);
            lp.y = pack_bf16(v[2] - hv[2], v[3] - hv[3]);
            uint32_t off = (uint32_t)edge * (AROW * 2) + (uint32_t)kq * 2;
            *(uint2*)(smem + SM_A_HI + off) = hp;
            *(uint2*)(smem + SM_A_LO + off) = lp;
        }

        int nxt = tile + EDGE_GRID;
        if (nxt < N_TILES) {
            int e0n = nxt * 128;
            int* sn = srcs + (buf ^ 1) * 128;
            int* dn = dsts + (buf ^ 1) * 128;
            float* en = eas + (buf ^ 1) * 512;
            if (t < 128) sn[t] = ei[e0n + t];
            else         dn[t - 128] = ei[N_EDGES + e0n + (t - 128)];
            for (int i = t; i < 512; i += 256) en[i] = ea[e0n * 4 + i];
        }
        __syncthreads();

        float acc[2][4][4];
#pragma unroll
        for (int mi = 0; mi < 2; mi++)
#pragma unroll
            for (int nn = 0; nn < 4; nn++)
#pragma unroll
                for (int r = 0; r < 4; r++) acc[mi][nn][r] = 0.f;

#pragma unroll
        for (int kk = 0; kk < 8; kk++) {
            uint32_t ahi[2][4], alo[2][4];
            uint32_t aoff = (uint32_t)(wm * 32 + lrow) * (AROW * 2)
                          + (uint32_t)(kk * 16 + lcol) * 2;
            ldsm4(ahi[0], smem_base + SM_A_HI + aoff);
            ldsm4(ahi[1], smem_base + SM_A_HI + aoff + 16 * (AROW * 2));
            ldsm4(alo[0], smem_base + SM_A_LO + aoff);
            ldsm4(alo[1], smem_base + SM_A_LO + aoff + 16 * (AROW * 2));

            uint32_t bh01[4], bh23[4], bl01[4], bl23[4];
            uint32_t boff = b_base + (uint32_t)kk * 32;
            ldsm4(bh01, smem_base + SM_B_HI + boff);
            ldsm4(bh23, smem_base + SM_B_HI + boff + 16 * (AROW * 2));
            ldsm4(bl01, smem_base + SM_B_LO + boff);
            ldsm4(bl23, smem_base + SM_B_LO + boff + 16 * (AROW * 2));
            uint32_t* bh[4] = {bh01, bh01 + 2, bh23, bh23 + 2};
            uint32_t* bl[4] = {bl01, bl01 + 2, bl23, bl23 + 2};

#pragma unroll
            for (int mi = 0; mi < 2; mi++) {
#pragma unroll
                for (int nn = 0; nn < 4; nn++) {
                    mma16816(acc[mi][nn], ahi[mi], bh[nn]);
                    mma16816(acc[mi][nn], ahi[mi], bl[nn]);
                    mma16816(acc[mi][nn], alo[mi], bh[nn]);
                }
            }
        }

        float part[2][2] = {{0.f, 0.f}, {0.f, 0.f}};
#pragma unroll
        for (int mi = 0; mi < 2; mi++) {
#pragma unroll
            for (int nn = 0; nn < 4; nn++) {
                int c0 = wn * 32 + nn * 8 + (lane & 3) * 2;
                float w30 = w3s[c0], w31 = w3s[c0 + 1];
                float bb0 = b2s[c0], bb1 = b2s[c0 + 1];
                part[mi][0] += fmaxf(acc[mi][nn][0] + bb0, 0.f) * w30
                             + fmaxf(acc[mi][nn][1] + bb1, 0.f) * w31;
                part[mi][1] += fmaxf(acc[mi][nn][2] + bb0, 0.f) * w30
                             + fmaxf(acc[mi][nn][3] + bb1, 0.f) * w31;
            }
        }
#pragma unroll
        for (int mi = 0; mi < 2; mi++) {
#pragma unroll
            for (int g = 0; g < 2; g++) {
                part[mi][g] += __shfl_xor_sync(0xffffffffu, part[mi][g], 1);
                part[mi][g] += __shfl_xor_sync(0xffffffffu, part[mi][g], 2);
            }
        }
        if ((lane & 3) == 0) {
            float* pw = wn ? pb : pa;
            int r0 = wm * 32 + (lane >> 2);
            pw[r0]      = part[0][0];
            pw[r0 + 8]  = part[0][1];
            pw[r0 + 16] = part[1][0];
            pw[r0 + 24] = part[1][1];
        }
        __syncthreads();
        if (t < 128) out[e0 + t] = pa[t] + pb[t] + be3v;
        buf ^= 1;
    }
}

// ---------------- launch ----------------
extern "C" void kernel_launch(void* const* d_in, const int* in_sizes, int n_in,
                              void* d_out, int out_size) {
    const float* x   = (const float*)d_in[0];
    const int*   ei  = (const int*)d_in[1];
    const float* ea  = (const float*)d_in[2];
    const float* w1r = (const float*)d_in[3];
    const float* w1n = (const float*)d_in[4];
    const float* b1  = (const float*)d_in[5];
    const float* w2r = (const float*)d_in[6];
    const float* w2n = (const float*)d_in[7];
    const float* b2  = (const float*)d_in[8];
    const float* we1 = (const float*)d_in[9];
    const float* be1 = (const float*)d_in[10];
    const float* we2 = (const float*)d_in[11];
    const float* be2 = (const float*)d_in[12];
    const float* we3 = (const float*)d_in[13];
    const float* be3 = (const float*)d_in[14];
    float* out = (float*)d_out;

    cudaFuncSetAttribute(k_node, cudaFuncAttributeMaxDynamicSharedMemorySize,
                         SM_NODE_TOTAL);
    cudaFuncSetAttribute(k_edge_mma, cudaFuncAttributeMaxDynamicSharedMemorySize,
                         SM_EDGE_TOTAL);

    k_zero<<<12500, 256>>>();
    k_agg1<<<N_EDGES / 256, 256>>>(x, ei);
    k_h1<<<N_NODES / 2, 256>>>(x, w1r, w1n, b1);
    k_agg2<<<N_EDGES / 8, 256>>>(ei);
    k_node<<<(N_NODES + 127) / 128, 256, SM_NODE_TOTAL>>>(w2r, w2n, b2, we1);
    k_edge_mma<<<EDGE_GRID, 256, SM_EDGE_TOTAL>>>(ei, ea, we1, be1, we2, be2, we3, be3, out);
}